// round 4
// baseline (speedup 1.0000x reference)
#include <cuda_runtime.h>
#include <cuda_bf16.h>

#define NB 128
#define THREADS 128
#define CHUNKS 6               // blocks per slice -> 24*6 = 144 blocks ~ 1 wave on 148 SMs
#define SLICE_F4 16384         // 65536 pixels per (B,C) slice = 16384 float4
#define CHUNK_F4 2731          // ceil(16384/6)

#define HW 0.00390625f         // half bin width = 1/256 (exact)
#define BIN_W 0.0078125f       // 1/128
#define LN101 0.009950330853155723f
#define INV_N 1.52587890625e-05f   // 1/65536

// x*128 is EXACT in fp32 (x in [0,1)), so trunc gives the true bin; centers
// (2b+1)/256 and the distance d are exact and bit-match the jnp reference.
// y = 1.01^d to first order keeps the reference's fp32 rounding cutoff:
// fma(d,ln101,1) > 1 iff d*ln101 > 2^-24, matching where fp32 pow rounds to
// exactly 1.0 (which the Threshold then zeroes).
__device__ __forceinline__ float yval(float x, int& bin) {
    float tf = x * 128.0f;
    int b = (int)tf;
    bin = b & 127;                            // smem bounds; sentinel -1 -> bin 0, y=0
    float c = fmaf((float)bin, BIN_W, HW);    // exact (2b+1)/256
    float d = HW - fabsf(x - c);
    float y = fmaf(d, LN101, 1.0f);
    return (y > 1.0f) ? y : 0.0f;             // exact-edge (d<=0) -> 0 too
}

// Two independent RMW streams (copies A and B) to overlap the LDS->FADD->STS chains.
// Streams never share an array, so within-thread same-bin pairs cannot lose updates.
__device__ __forceinline__ void acc2(float xa, float xb, float* __restrict__ A,
                                     float* __restrict__ B, int tid) {
    int ba, bb;
    float ya = yval(xa, ba);
    float yb = yval(xb, bb);
    float* pa = &A[ba * THREADS + tid];
    float* pb = &B[bb * THREADS + tid];
    float va = *pa;
    float vb = *pb;
    *pa = va + ya;      // adding 0.0f when thresholded is exact and branch-free
    *pb = vb + yb;
}

__device__ __forceinline__ void acc4(float4 v, float* __restrict__ A,
                                     float* __restrict__ B, int tid) {
    acc2(v.x, v.y, A, B, tid);
    acc2(v.z, v.w, A, B, tid);
}

__global__ void __launch_bounds__(THREADS) zero_kernel(float* out, int n) {
    int i = blockIdx.x * blockDim.x + threadIdx.x;
    if (i < n) out[i] = 0.0f;
}

__global__ void __launch_bounds__(THREADS, 1) hist_kernel(const float* __restrict__ in,
                                                          float* __restrict__ out) {
    extern __shared__ float sh[];              // 2 * 128 * 128 floats = 128 KB
    const int tid = threadIdx.x;
    float* __restrict__ A = sh;
    float* __restrict__ B = sh + NB * THREADS;

    // zero both copies: 32768 floats / 128 threads = 64 float4 stores per thread
    {
        float4 z = make_float4(0.f, 0.f, 0.f, 0.f);
        float4* sh4 = (float4*)sh;
#pragma unroll
        for (int q = 0; q < (2 * NB * THREADS / 4) / THREADS; q++)
            sh4[q * THREADS + tid] = z;
    }
    __syncthreads();

    const int slice = blockIdx.y;
    const float4* p = (const float4*)in + (size_t)slice * SLICE_F4;
    const int start = blockIdx.x * CHUNK_F4;
    const int end = min(start + CHUNK_F4, SLICE_F4);

    // software-pipelined stream: 4 float4 in flight (L2-resident after 1st replay)
    const float4 sentinel = make_float4(-1.f, -1.f, -1.f, -1.f);  // yval(-1)=0
    int i0 = start + tid;
    float4 v0 = (i0 + 0 * THREADS < end) ? p[i0 + 0 * THREADS] : sentinel;
    float4 v1 = (i0 + 1 * THREADS < end) ? p[i0 + 1 * THREADS] : sentinel;
    float4 v2 = (i0 + 2 * THREADS < end) ? p[i0 + 2 * THREADS] : sentinel;
    float4 v3 = (i0 + 3 * THREADS < end) ? p[i0 + 3 * THREADS] : sentinel;

    for (int base = i0; base < end; base += 4 * THREADS) {
        int nb0 = base + 4 * THREADS;
        float4 n0 = (nb0 + 0 * THREADS < end) ? p[nb0 + 0 * THREADS] : sentinel;
        float4 n1 = (nb0 + 1 * THREADS < end) ? p[nb0 + 1 * THREADS] : sentinel;
        float4 n2 = (nb0 + 2 * THREADS < end) ? p[nb0 + 2 * THREADS] : sentinel;
        float4 n3 = (nb0 + 3 * THREADS < end) ? p[nb0 + 3 * THREADS] : sentinel;

        acc4(v0, A, B, tid);
        acc4(v1, A, B, tid);
        acc4(v2, A, B, tid);
        acc4(v3, A, B, tid);

        v0 = n0; v1 = n1; v2 = n2; v3 = n3;
    }
    __syncthreads();

    // reduce: thread t owns bin t; staggered float4 reads -> conflict-free LDS.128
    {
        const int t = tid;
        const float4* A4 = (const float4*)(A + t * THREADS);
        const float4* B4 = (const float4*)(B + t * THREADS);
        float4 sa = make_float4(0.f, 0.f, 0.f, 0.f);
        float4 sb = make_float4(0.f, 0.f, 0.f, 0.f);
#pragma unroll 8
        for (int k = 0; k < THREADS / 4; k++) {
            int j = (k + t) & (THREADS / 4 - 1);
            float4 a = A4[j];
            float4 b = B4[j];
            sa.x += a.x; sa.y += a.y; sa.z += a.z; sa.w += a.w;
            sb.x += b.x; sb.y += b.y; sb.z += b.z; sb.w += b.w;
        }
        float s = ((sa.x + sa.y) + (sa.z + sa.w)) + ((sb.x + sb.y) + (sb.z + sb.w));
        atomicAdd(&out[slice * NB + t], s * INV_N);
    }
}

extern "C" void kernel_launch(void* const* d_in, const int* in_sizes, int n_in,
                              void* d_out, int out_size) {
    const float* in = (const float*)d_in[0];
    float* out = (float*)d_out;

    const int n_pixels = in_sizes[0];
    const int n_slices = n_pixels / (SLICE_F4 * 4);   // B*C = 24

    const int smem = 2 * NB * THREADS * (int)sizeof(float);   // 131072
    cudaFuncSetAttribute(hist_kernel, cudaFuncAttributeMaxDynamicSharedMemorySize, smem);

    zero_kernel<<<(out_size + THREADS - 1) / THREADS, THREADS>>>(out, out_size);

    dim3 grid(CHUNKS, n_slices);
    hist_kernel<<<grid, THREADS, smem>>>(in, out);
}